// round 15
// baseline (speedup 1.0000x reference)
#include <cuda_runtime.h>
#include <cuda_fp16.h>
#include <math.h>
#include <stdint.h>

#define EPS_LN  1e-5f
#define EPS_ATT 1e-6f

// ---------------------------------------------------------------------------
// helpers
// ---------------------------------------------------------------------------
__device__ __forceinline__ uint32_t smem_u32(const void* p) {
    uint32_t a;
    asm("{ .reg .u64 t; cvta.to.shared.u64 t, %1; cvt.u32.u64 %0, t; }" : "=r"(a) : "l"(p));
    return a;
}
__device__ __forceinline__ void mma16(float* c, const uint32_t* a, const uint32_t* b) {
    asm volatile(
        "mma.sync.aligned.m16n8k16.row.col.f32.f16.f16.f32 "
        "{%0,%1,%2,%3}, {%4,%5,%6,%7}, {%8,%9}, {%0,%1,%2,%3};"
        : "+f"(c[0]), "+f"(c[1]), "+f"(c[2]), "+f"(c[3])
        : "r"(a[0]), "r"(a[1]), "r"(a[2]), "r"(a[3]), "r"(b[0]), "r"(b[1]));
}
__device__ __forceinline__ void ldsm_x4(uint32_t& r0, uint32_t& r1, uint32_t& r2, uint32_t& r3,
                                        uint32_t addr) {
    asm volatile("ldmatrix.sync.aligned.m8n8.x4.shared.b16 {%0,%1,%2,%3}, [%4];"
        : "=r"(r0), "=r"(r1), "=r"(r2), "=r"(r3) : "r"(addr));
}
__device__ __forceinline__ uint32_t h2u(__half2 h) { return *(uint32_t*)&h; }

// ---------------------------------------------------------------------------
// Scratch
// ---------------------------------------------------------------------------
__device__ __half g_wsrB[256 * 4096];
__device__ __half g_wqr [256 * 256];
__device__ __half g_wkr [256 * 256];
__device__ __half g_wvr [256 * 256];
__device__ __half g_wmr [256 * 256];
__device__ __half g_w1r [512 * 512];
__device__ __half g_w2r [256 * 512];
__device__ __half g_xh  [8 * 4096 * 256];
__device__ __half g_part[8 * 2048 * 256];
__device__ __half g_src [2048 * 256];
__device__ __half g_kmat[2048 * 256];
__device__ __half g_vmat[2048 * 256];
__device__ float  g_kv  [64 * 32 * 32];
__device__ float  g_ksum[64 * 32];
__device__ __half g_msg [8 * 4096 * 256];
__device__ __half g_msgn[8 * 4096 * 256];
__device__ __half g_hmid[8 * 4096 * 512];

// ---------------------------------------------------------------------------
// Unified prep. grid 11008 x 256.
// ---------------------------------------------------------------------------
__global__ void prep_all(const float* __restrict__ x,
                         const float* __restrict__ sr_w,
                         const float* __restrict__ wq, const float* __restrict__ wk,
                         const float* __restrict__ wv, const float* __restrict__ wm,
                         const float* __restrict__ w1, const float* __restrict__ w2,
                         __half* __restrict__ xh, __half* __restrict__ wsrB,
                         __half* __restrict__ oq, __half* __restrict__ ok,
                         __half* __restrict__ ov, __half* __restrict__ om,
                         __half* __restrict__ o1, __half* __restrict__ o2) {
    int bid = blockIdx.x;
    if (bid < 8192) {
        size_t i = ((size_t)bid * 256 + threadIdx.x) * 4;
        float4 v = *(const float4*)&x[i];
        __half2 h0 = __floats2half2_rn(v.x, v.y);
        __half2 h1 = __floats2half2_rn(v.z, v.w);
        *(uint2*)&xh[i] = make_uint2(h2u(h0), h2u(h1));
        return;
    }
    bid -= 8192;
    if (bid < 2560) {
        const float* src; __half* dst; int base;
        if      (bid < 256)  { src = wq; dst = oq; base = 0; }
        else if (bid < 512)  { src = wk; dst = ok; base = 256; }
        else if (bid < 768)  { src = wv; dst = ov; base = 512; }
        else if (bid < 1024) { src = wm; dst = om; base = 768; }
        else if (bid < 2048) { src = w1; dst = o1; base = 1024; }
        else                 { src = w2; dst = o2; base = 2048; }
        int idx = (bid - base) * 256 + threadIdx.x;
        dst[idx] = __float2half_rn(src[idx]);
        return;
    }
    bid -= 2560;
    {
        int idx = bid * 256 + threadIdx.x;
        int o = idx >> 8, i = idx & 255;
        const float* p = sr_w + ((size_t)(o * 256 + i)) * 16;
#pragma unroll
        for (int rr = 0; rr < 16; rr++)
            wsrB[(size_t)o * 4096 + rr * 256 + i] = __float2half_rn(p[rr]);
    }
}

// ---------------------------------------------------------------------------
// Split-K(8) reduce + bias + LayerNorm -> src (fp16). grid 256, 256 thr.
// ---------------------------------------------------------------------------
__global__ void reduce_ln(const __half* __restrict__ part, const float* __restrict__ bias,
                          const float* __restrict__ g, const float* __restrict__ bb,
                          __half* __restrict__ out) {
    int lane = threadIdx.x & 31, w = threadIdx.x >> 5;
    int row = blockIdx.x * 8 + w;
    float v[8];
#pragma unroll
    for (int j = 0; j < 8; j++) {
        int c = lane + j * 32;
        float s = 0.f;
#pragma unroll
        for (int ks = 0; ks < 8; ks++)
            s += __half2float(part[((size_t)ks * 2048 + row) * 256 + c]);
        v[j] = s + bias[c];
    }
    float sum = 0.f;
#pragma unroll
    for (int j = 0; j < 8; j++) sum += v[j];
#pragma unroll
    for (int o = 16; o; o >>= 1) sum += __shfl_xor_sync(0xffffffffu, sum, o);
    float mean = sum * (1.f / 256.f);
    float ss = 0.f;
#pragma unroll
    for (int j = 0; j < 8; j++) { float d = v[j] - mean; ss += d * d; }
#pragma unroll
    for (int o = 16; o; o >>= 1) ss += __shfl_xor_sync(0xffffffffu, ss, o);
    float inv = rsqrtf(ss * (1.f / 256.f) + EPS_LN);
#pragma unroll
    for (int j = 0; j < 8; j++) {
        int c = lane + j * 32;
        out[(size_t)row * 256 + c] = __float2half_rn((v[j] - mean) * inv * g[c] + bb[c]);
    }
}

// ---------------------------------------------------------------------------
// fp16 mma GEMM, BK=64 halfs, 2-stage double buffer (R13 schedule).
// BM=128, BN=NB, 256 thr, ldmatrix fragments.
// EPI: 0 plain, 1 elu+1, 2 relu, 3 LN, 4 LN+resid, 5 fused attention
// ---------------------------------------------------------------------------
#define EPI_PLAIN    0
#define EPI_ELU1     1
#define EPI_RELU     2
#define EPI_LN       3
#define EPI_LN_RESID 4
#define EPI_ATTN     5

#define RSTRIDE_H 72
#define A_ROWS    128

__host__ __device__ constexpr int stage_halfs(int NB) { return (128 + NB) * RSTRIDE_H; }
__host__ __device__ constexpr int smem_req(int NB, int EPI) {
    int mainloop = 2 * stage_halfs(NB) * 2;
    int epi = (128 * (NB + 4) + 256) * 4;
    if (EPI == EPI_ATTN) epi = (128 * (NB + 4) + 512 + 128 + 4096) * 4;
    return mainloop > epi ? mainloop : epi;
}

template <int EPI, int MODE, int NB, bool OUTH>
__global__ __launch_bounds__(256, (NB == 128 ? 2 : 1))
void mma_gemm(const __half* __restrict__ A0, const __half* __restrict__ A1,
              const __half* __restrict__ Bw, void* __restrict__ Cv,
              int Kloc, int KB, int Ntot,
              const float* __restrict__ gamma, const float* __restrict__ beta,
              const float* __restrict__ resid,
              const __half* __restrict__ Bw2, void* __restrict__ C2v) {
    extern __shared__ __half dsm_h[];

    constexpr int WM    = (NB == 256) ? 2 : 4;
    constexpr int MF    = 128 / WM / 16;
    constexpr int MROWS = 128 / WM;
    constexpr int BLD   = NB / 32;
    constexpr int STAGE = stage_halfs(NB);
    constexpr int EPIST = NB + 4;

    const int tid  = threadIdx.x;
    const int lane = tid & 31;
    const int wid  = tid >> 5;
    const int g    = lane >> 2;
    const int t    = lane & 3;
    const int warp_m = wid % WM;
    const int warp_n = wid / WM;

    const int mtile = blockIdx.x * 128;
    int ncol0 = blockIdx.y * NB, kstart = 0;
    const __half* Bsrc = Bw;
    void* Cout = Cv;
    size_t coff = 0;
    if (MODE == 2) { kstart = blockIdx.z * 512; coff = (size_t)blockIdx.z * 2048 * 256; }
    if (MODE == 3) { if (blockIdx.z) { Bsrc = Bw2; Cout = C2v; } }
    const int KT = Kloc / 64;

    float acc[MF][8][4];
#pragma unroll
    for (int i = 0; i < MF; i++)
#pragma unroll
        for (int j = 0; j < 8; j++)
#pragma unroll
            for (int q = 0; q < 4; q++) acc[i][j][q] = 0.f;

    uint4 rA[4], rB[BLD];

    auto ldg_tile = [&](int kt) {
        const int kbase = kstart + kt * 64;
#pragma unroll
        for (int p = 0; p < 4; p++) {
            int idx = p * 256 + tid;
            int m = idx >> 3, c = idx & 7;
            int kk = kbase + c * 8;
            const __half* gp;
            if (MODE == 2) {
                int mg = mtile + m;
                int b = mg >> 8, s5 = mg & 255;
                int rr = kk >> 8, i = kk & 255;
                int n = (((s5 >> 4) * 4 + (rr >> 2)) << 6) + ((s5 & 15) << 2) + (rr & 3);
                gp = A0 + (((size_t)b << 12) + n) * 256 + i;
            } else if (MODE == 1) {
                gp = (kk < 256) ? (A0 + (size_t)(mtile + m) * 256 + kk)
                                : (A1 + (size_t)(mtile + m) * 256 + (kk - 256));
            } else {
                gp = A0 + (size_t)(mtile + m) * Kloc + kk;
            }
            rA[p] = *(const uint4*)gp;
        }
#pragma unroll
        for (int p = 0; p < BLD; p++) {
            int idx = p * 256 + tid;
            int n = idx >> 3, c = idx & 7;
            rB[p] = *(const uint4*)(Bsrc + (size_t)(ncol0 + n) * KB + kbase + c * 8);
        }
    };
    auto sts_tile = [&](int s) {
        __half* sA = dsm_h + s * STAGE;
        __half* sB = sA + A_ROWS * RSTRIDE_H;
#pragma unroll
        for (int p = 0; p < 4; p++) {
            int idx = p * 256 + tid;
            int m = idx >> 3, c = idx & 7;
            *(uint4*)&sA[m * RSTRIDE_H + c * 8] = rA[p];
        }
#pragma unroll
        for (int p = 0; p < BLD; p++) {
            int idx = p * 256 + tid;
            int n = idx >> 3, c = idx & 7;
            *(uint4*)&sB[n * RSTRIDE_H + c * 8] = rB[p];
        }
    };

    const uint32_t smb = smem_u32(dsm_h);
    const uint32_t a_l = ((warp_m * MROWS + (lane & 7) + ((lane >> 3) & 1) * 8) * RSTRIDE_H
                          + ((lane >> 4) & 1) * 8) * 2;
    const uint32_t b_l = ((A_ROWS + warp_n * 64 + (lane & 7) + ((lane >> 4) & 1) * 8) * RSTRIDE_H
                          + ((lane >> 3) & 1) * 8) * 2;

    ldg_tile(0);
    sts_tile(0);
    if (KT > 1) ldg_tile(1);
    __syncthreads();

    for (int kt = 0; kt < KT; kt++) {
        if (kt + 1 < KT) {
            sts_tile((kt + 1) & 1);
            if (kt + 2 < KT) ldg_tile(kt + 2);
            __syncthreads();
        }
        const uint32_t sbase = smb + (uint32_t)(kt & 1) * (STAGE * 2);
#pragma unroll
        for (int ks = 0; ks < 4; ks++) {
            const uint32_t koffB = ks * 32;
            uint32_t a[MF][4], b[8][2];
#pragma unroll
            for (int mf = 0; mf < MF; mf++)
                ldsm_x4(a[mf][0], a[mf][1], a[mf][2], a[mf][3],
                        sbase + a_l + mf * (16 * RSTRIDE_H * 2) + koffB);
#pragma unroll
            for (int p = 0; p < 4; p++)
                ldsm_x4(b[2 * p][0], b[2 * p][1], b[2 * p + 1][0], b[2 * p + 1][1],
                        sbase + b_l + p * (16 * RSTRIDE_H * 2) + koffB);
#pragma unroll
            for (int mf = 0; mf < MF; mf++)
#pragma unroll
                for (int nf = 0; nf < 8; nf++)
                    mma16(acc[mf][nf], a[mf], b[nf]);
        }
        __syncthreads();
    }

    // ---- epilogue ----
    float* sepi   = (float*)dsm_h;
    float* s_mean = sepi + 128 * EPIST;
    float* s_inv  = s_mean + 128;
    float* z_s    = sepi + 128 * EPIST;
    float* ksum_s = z_s + 512;
    float* kv_s   = ksum_s + 128;
    const bool doAct = (MODE != 3) || (blockIdx.z == 0);

    if (EPI == EPI_ATTN) {
        const int b = mtile >> 12;
        const int H0 = blockIdx.y * 4;
        const float4* kvg = (const float4*)(gamma + (((size_t)(b * 8 + H0)) * 32) * 32);
#pragma unroll
        for (int p = 0; p < 4; p++)
            *(float4*)&kv_s[(p * 256 + tid) * 4] = kvg[p * 256 + tid];
        if (tid < 32)
            *(float4*)&ksum_s[tid * 4] = *(const float4*)(beta + b * 256 + H0 * 32 + tid * 4);
    }

#pragma unroll
    for (int mf = 0; mf < MF; mf++) {
        int r0 = warp_m * MROWS + mf * 16 + g;
#pragma unroll
        for (int nf = 0; nf < 8; nf++) {
            int c0 = warp_n * 64 + nf * 8 + 2 * t;
            float v0 = acc[mf][nf][0], v1 = acc[mf][nf][1];
            float v2 = acc[mf][nf][2], v3 = acc[mf][nf][3];
            if ((EPI == EPI_ELU1 || EPI == EPI_ATTN) && doAct) {
                v0 = (v0 > 0.f) ? v0 + 1.f : __expf(v0);
                v1 = (v1 > 0.f) ? v1 + 1.f : __expf(v1);
                v2 = (v2 > 0.f) ? v2 + 1.f : __expf(v2);
                v3 = (v3 > 0.f) ? v3 + 1.f : __expf(v3);
            }
            if (EPI == EPI_RELU) {
                v0 = fmaxf(v0, 0.f); v1 = fmaxf(v1, 0.f);
                v2 = fmaxf(v2, 0.f); v3 = fmaxf(v3, 0.f);
            }
            *(float2*)&sepi[r0 * EPIST + c0]       = make_float2(v0, v1);
            *(float2*)&sepi[(r0 + 8) * EPIST + c0] = make_float2(v2, v3);
        }
    }
    __syncthreads();

    if (EPI == EPI_ATTN) {
#pragma unroll
        for (int i = 0; i < 2; i++) {
            int p = tid * 2 + i;
            int row = p >> 2, hh = p & 3;
            const float4* qp = (const float4*)&sepi[row * EPIST + hh * 32];
            const float4* kp = (const float4*)&ksum_s[hh * 32];
            float z = 0.f;
#pragma unroll
            for (int q4 = 0; q4 < 8; q4++) {
                float4 qv = qp[q4], kv4 = kp[q4];
                z += qv.x * kv4.x + qv.y * kv4.y + qv.z * kv4.z + qv.w * kv4.w;
            }
            z_s[p] = 1.f / (z + EPS_ATT);
        }
        __syncthreads();

        const int c  = tid & 31;
        const int hf = (tid >> 5) & 1;
        const int hh = tid >> 6;
        float kvr[32];
#pragma unroll
        for (int d = 0; d < 32; d++) kvr[d] = kv_s[hh * 1024 + d * 32 + c];
        __half* msgp = (__half*)Cout;
        const int colg = blockIdx.y * 128 + hh * 32 + c;
#pragma unroll 2
        for (int r = 0; r < 64; r++) {
            int row = hf * 64 + r;
            const float4* qp = (const float4*)&sepi[row * EPIST + hh * 32];
            float m = 0.f;
#pragma unroll
            for (int q4 = 0; q4 < 8; q4++) {
                float4 qv = qp[q4];
                m += qv.x * kvr[q4 * 4] + qv.y * kvr[q4 * 4 + 1]
                   + qv.z * kvr[q4 * 4 + 2] + qv.w * kvr[q4 * 4 + 3];
            }
            m *= z_s[row * 4 + hh];
            msgp[(size_t)(mtile + row) * 256 + colg] = __float2half_rn(m);
        }
        return;
    }

    if ((EPI == EPI_LN || EPI == EPI_LN_RESID) && tid < 128) {
        const float* rowp = sepi + tid * EPIST;
        float sum = 0.f, ss = 0.f;
#pragma unroll 8
        for (int j = 0; j < NB / 4; j++) {
            float4 v = *(const float4*)&rowp[j * 4];
            sum += v.x + v.y + v.z + v.w;
            ss  += v.x * v.x + v.y * v.y + v.z * v.z + v.w * v.w;
        }
        float mean = sum * (1.f / 256.f);
        float var  = ss * (1.f / 256.f) - mean * mean;
        s_mean[tid] = mean;
        s_inv[tid]  = rsqrtf(var + EPS_LN);
    }
    if (EPI == EPI_LN || EPI == EPI_LN_RESID) __syncthreads();

#pragma unroll 4
    for (int p = 0; p < NB / 8; p++) {
        int idx4 = p * 256 + tid;
        int row = idx4 / (NB / 4);
        int c4  = (idx4 % (NB / 4)) << 2;
        float4 v = *(const float4*)&sepi[row * EPIST + c4];
        if (EPI == EPI_LN || EPI == EPI_LN_RESID) {
            float m = s_mean[row], iv = s_inv[row];
            float4 gm = *(const float4*)&gamma[c4];
            float4 bt = *(const float4*)&beta[c4];
            v.x = (v.x - m) * iv * gm.x + bt.x;
            v.y = (v.y - m) * iv * gm.y + bt.y;
            v.z = (v.z - m) * iv * gm.z + bt.z;
            v.w = (v.w - m) * iv * gm.w + bt.w;
            if (EPI == EPI_LN_RESID) {
                float4 r = *(const float4*)&resid[(size_t)(mtile + row) * 256 + c4];
                v.x += r.x; v.y += r.y; v.z += r.z; v.w += r.w;
            }
        }
        size_t off = coff + (size_t)(mtile + row) * Ntot + ncol0 + c4;
        if (OUTH) {
            __half2 h0 = __floats2half2_rn(v.x, v.y);
            __half2 h1 = __floats2half2_rn(v.z, v.w);
            *(uint2*)&((__half*)Cout)[off] = make_uint2(h2u(h0), h2u(h1));
        } else {
            *(float4*)&((float*)Cout)[off] = v;
        }
    }
}

// ---------------------------------------------------------------------------
// KV = sum_s K^T V, Ksum = sum_s K. fp16 in, fp32 math. grid 64, 256 thr.
// ---------------------------------------------------------------------------
__global__ void kv_kernel(const __half* __restrict__ kmat, const __half* __restrict__ vmat,
                          float* __restrict__ kv, float* __restrict__ ksum) {
    __shared__ float Ks[128][32];
    __shared__ float Vs[128][32];
    int bh = blockIdx.x, b = bh >> 3, h = bh & 7;
    int tid = threadIdx.x;
    int d = tid & 31, vg = tid >> 5;
    float acc0 = 0.f, acc1 = 0.f, acc2 = 0.f, acc3 = 0.f, ka = 0.f;

    for (int ch = 0; ch < 2; ch++) {
        int sl = tid >> 3, c4 = tid & 7;
#pragma unroll
        for (int ss = 0; ss < 4; ss++) {
            int srow = ch * 128 + ss * 32 + sl;
            size_t base = ((size_t)(b * 256 + srow)) * 256 + h * 32 + c4 * 4;
            uint2 kw = *(const uint2*)&kmat[base];
            uint2 vw = *(const uint2*)&vmat[base];
            __half2* kh = (__half2*)&kw;
            __half2* vh = (__half2*)&vw;
            float2 k0 = __half22float2(kh[0]), k1 = __half22float2(kh[1]);
            float2 w0 = __half22float2(vh[0]), w1 = __half22float2(vh[1]);
            Ks[ss * 32 + sl][c4 * 4 + 0] = k0.x; Ks[ss * 32 + sl][c4 * 4 + 1] = k0.y;
            Ks[ss * 32 + sl][c4 * 4 + 2] = k1.x; Ks[ss * 32 + sl][c4 * 4 + 3] = k1.y;
            Vs[ss * 32 + sl][c4 * 4 + 0] = w0.x; Vs[ss * 32 + sl][c4 * 4 + 1] = w0.y;
            Vs[ss * 32 + sl][c4 * 4 + 2] = w1.x; Vs[ss * 32 + sl][c4 * 4 + 3] = w1.y;
        }
        __syncthreads();
#pragma unroll 4
        for (int s = 0; s < 128; s++) {
            float kd = Ks[s][d];
            float4 vv = *(float4*)&Vs[s][vg * 4];
            acc0 += kd * vv.x; acc1 += kd * vv.y;
            acc2 += kd * vv.z; acc3 += kd * vv.w;
            if (vg == 0) ka += kd;
        }
        __syncthreads();
    }
    float* kvp = kv + ((size_t)bh * 32 + d) * 32 + vg * 4;
    kvp[0] = acc0; kvp[1] = acc1; kvp[2] = acc2; kvp[3] = acc3;
    if (vg == 0) ksum[bh * 32 + d] = ka;
}

// ---------------------------------------------------------------------------
// Launch
// ---------------------------------------------------------------------------
extern "C" void kernel_launch(void* const* d_in, const int* in_sizes, int n_in,
                              void* d_out, int out_size) {
    const float* x      = (const float*)d_in[0];
    const float* sr_w   = (const float*)d_in[1];
    const float* sr_b   = (const float*)d_in[2];
    const float* norm_g = (const float*)d_in[3];
    const float* norm_b = (const float*)d_in[4];
    const float* wq     = (const float*)d_in[5];
    const float* wk     = (const float*)d_in[6];
    const float* wv     = (const float*)d_in[7];
    const float* wm     = (const float*)d_in[8];
    const float* w1     = (const float*)d_in[9];
    const float* w2     = (const float*)d_in[10];
    const float* n1g    = (const float*)d_in[11];
    const float* n1b    = (const float*)d_in[12];
    const float* n2g    = (const float*)d_in[13];
    const float* n2b    = (const float*)d_in[14];
    float* out = (float*)d_out;

    __half *wsrB, *wqr, *wkr, *wvr, *wmr, *w1r, *w2r;
    __half *xh, *part, *src, *kmat, *vmat, *msg, *msgn, *hmid;
    float *kvp, *ksump;
    cudaGetSymbolAddress((void**)&wsrB, g_wsrB);
    cudaGetSymbolAddress((void**)&wqr,  g_wqr);
    cudaGetSymbolAddress((void**)&wkr,  g_wkr);
    cudaGetSymbolAddress((void**)&wvr,  g_wvr);
    cudaGetSymbolAddress((void**)&wmr,  g_wmr);
    cudaGetSymbolAddress((void**)&w1r,  g_w1r);
    cudaGetSymbolAddress((void**)&w2r,  g_w2r);
    cudaGetSymbolAddress((void**)&xh,   g_xh);
    cudaGetSymbolAddress((void**)&part, g_part);
    cudaGetSymbolAddress((void**)&src,  g_src);
    cudaGetSymbolAddress((void**)&kmat, g_kmat);
    cudaGetSymbolAddress((void**)&vmat, g_vmat);
    cudaGetSymbolAddress((void**)&kvp,  g_kv);
    cudaGetSymbolAddress((void**)&ksump,g_ksum);
    cudaGetSymbolAddress((void**)&msg,  g_msg);
    cudaGetSymbolAddress((void**)&msgn, g_msgn);
    cudaGetSymbolAddress((void**)&hmid, g_hmid);

    constexpr int SM128  = smem_req(128, EPI_PLAIN);
    constexpr int SMATTN = smem_req(128, EPI_ATTN);
    constexpr int SM256  = smem_req(256, EPI_LN);
    cudaFuncSetAttribute(mma_gemm<EPI_PLAIN, 2, 128, true>,    cudaFuncAttributeMaxDynamicSharedMemorySize, SM128);
    cudaFuncSetAttribute(mma_gemm<EPI_ELU1, 3, 128, true>,     cudaFuncAttributeMaxDynamicSharedMemorySize, SM128);
    cudaFuncSetAttribute(mma_gemm<EPI_ATTN, 0, 128, true>,     cudaFuncAttributeMaxDynamicSharedMemorySize, SMATTN);
    cudaFuncSetAttribute(mma_gemm<EPI_RELU, 1, 128, true>,     cudaFuncAttributeMaxDynamicSharedMemorySize, SM128);
    cudaFuncSetAttribute(mma_gemm<EPI_LN, 0, 256, true>,       cudaFuncAttributeMaxDynamicSharedMemorySize, SM256);
    cudaFuncSetAttribute(mma_gemm<EPI_LN_RESID, 0, 256, false>,cudaFuncAttributeMaxDynamicSharedMemorySize, SM256);

    prep_all<<<11008, 256>>>(x, sr_w, wq, wk, wv, wm, w1, w2,
                             xh, wsrB, wqr, wkr, wvr, wmr, w1r, w2r);

    // conv-as-GEMM (split-K=8 on z) + reduce/bias/LN -> src
    mma_gemm<EPI_PLAIN, 2, 128, true><<<dim3(16, 2, 8), 256, SM128>>>(
        xh, nullptr, wsrB, part, 512, 4096, 256, nullptr, nullptr, nullptr, nullptr, nullptr);
    reduce_ln<<<256, 256>>>(part, sr_b, norm_g, norm_b, src);

    // fused k/v projections (M=2048)
    mma_gemm<EPI_ELU1, 3, 128, true><<<dim3(16, 2, 2), 256, SM128>>>(
        src, nullptr, wkr, kmat, 256, 256, 256, nullptr, nullptr, nullptr, wvr, vmat);

    kv_kernel<<<64, 256>>>(kmat, vmat, kvp, ksump);

    // q projection + fused linear attention -> msg
    mma_gemm<EPI_ATTN, 0, 128, true><<<dim3(256, 2), 256, SMATTN>>>(
        xh, nullptr, wqr, msg, 256, 256, 256, kvp, ksump, nullptr, nullptr, nullptr);

    // merge projection + LN1
    mma_gemm<EPI_LN, 0, 256, true><<<dim3(256, 1), 256, SM256>>>(
        msg, nullptr, wmr, msgn, 256, 256, 256, n1g, n1b, nullptr, nullptr, nullptr);

    // MLP1: concat(xh, msgn) @ w1^T -> relu
    mma_gemm<EPI_RELU, 1, 128, true><<<dim3(256, 4), 256, SM128>>>(
        xh, msgn, w1r, hmid, 512, 512, 512, nullptr, nullptr, nullptr, nullptr, nullptr);

    // MLP2 + LN2 + residual -> out (fp32)
    mma_gemm<EPI_LN_RESID, 0, 256, false><<<dim3(256, 1), 256, SM256>>>(
        hmid, nullptr, w2r, out, 512, 512, 256, n2g, n2b, x, nullptr, nullptr);
}

// round 16
// speedup vs baseline: 1.2938x; 1.2938x over previous
#include <cuda_runtime.h>
#include <cuda_fp16.h>
#include <math.h>
#include <stdint.h>

#define EPS_LN  1e-5f
#define EPS_ATT 1e-6f

// ---------------------------------------------------------------------------
// helpers
// ---------------------------------------------------------------------------
__device__ __forceinline__ uint32_t smem_u32(const void* p) {
    uint32_t a;
    asm("{ .reg .u64 t; cvta.to.shared.u64 t, %1; cvt.u32.u64 %0, t; }" : "=r"(a) : "l"(p));
    return a;
}
__device__ __forceinline__ void mma16(float* c, const uint32_t* a, const uint32_t* b) {
    asm volatile(
        "mma.sync.aligned.m16n8k16.row.col.f32.f16.f16.f32 "
        "{%0,%1,%2,%3}, {%4,%5,%6,%7}, {%8,%9}, {%0,%1,%2,%3};"
        : "+f"(c[0]), "+f"(c[1]), "+f"(c[2]), "+f"(c[3])
        : "r"(a[0]), "r"(a[1]), "r"(a[2]), "r"(a[3]), "r"(b[0]), "r"(b[1]));
}
__device__ __forceinline__ void ldsm_x4(uint32_t& r0, uint32_t& r1, uint32_t& r2, uint32_t& r3,
                                        uint32_t addr) {
    asm volatile("ldmatrix.sync.aligned.m8n8.x4.shared.b16 {%0,%1,%2,%3}, [%4];"
        : "=r"(r0), "=r"(r1), "=r"(r2), "=r"(r3) : "r"(addr));
}
__device__ __forceinline__ uint32_t h2u(__half2 h) { return *(uint32_t*)&h; }

// ---------------------------------------------------------------------------
// Scratch
// ---------------------------------------------------------------------------
__device__ __half g_wsrB[256 * 4096];
__device__ __half g_wqr [256 * 256];
__device__ __half g_wkr [256 * 256];
__device__ __half g_wvr [256 * 256];
__device__ __half g_wmr [256 * 256];
__device__ __half g_w1r [512 * 512];
__device__ __half g_w2r [256 * 512];
__device__ __half g_xh  [8 * 4096 * 256];
__device__ __half g_part[8 * 2048 * 256];
__device__ __half g_src [2048 * 256];
__device__ __half g_kmat[2048 * 256];
__device__ __half g_vmat[2048 * 256];
__device__ float  g_kv  [64 * 32 * 32];
__device__ float  g_ksum[64 * 32];
__device__ __half g_msg [8 * 4096 * 256];
__device__ __half g_msgn[8 * 4096 * 256];
__device__ __half g_hmid[8 * 4096 * 512];

// ---------------------------------------------------------------------------
// Unified prep. grid 11008 x 256.
// ---------------------------------------------------------------------------
__global__ void prep_all(const float* __restrict__ x,
                         const float* __restrict__ sr_w,
                         const float* __restrict__ wq, const float* __restrict__ wk,
                         const float* __restrict__ wv, const float* __restrict__ wm,
                         const float* __restrict__ w1, const float* __restrict__ w2,
                         __half* __restrict__ xh, __half* __restrict__ wsrB,
                         __half* __restrict__ oq, __half* __restrict__ ok,
                         __half* __restrict__ ov, __half* __restrict__ om,
                         __half* __restrict__ o1, __half* __restrict__ o2) {
    int bid = blockIdx.x;
    if (bid < 8192) {
        size_t i = ((size_t)bid * 256 + threadIdx.x) * 4;
        float4 v = *(const float4*)&x[i];
        __half2 h0 = __floats2half2_rn(v.x, v.y);
        __half2 h1 = __floats2half2_rn(v.z, v.w);
        *(uint2*)&xh[i] = make_uint2(h2u(h0), h2u(h1));
        return;
    }
    bid -= 8192;
    if (bid < 2560) {
        const float* src; __half* dst; int base;
        if      (bid < 256)  { src = wq; dst = oq; base = 0; }
        else if (bid < 512)  { src = wk; dst = ok; base = 256; }
        else if (bid < 768)  { src = wv; dst = ov; base = 512; }
        else if (bid < 1024) { src = wm; dst = om; base = 768; }
        else if (bid < 2048) { src = w1; dst = o1; base = 1024; }
        else                 { src = w2; dst = o2; base = 2048; }
        int idx = (bid - base) * 256 + threadIdx.x;
        dst[idx] = __float2half_rn(src[idx]);
        return;
    }
    bid -= 2560;
    {
        int idx = bid * 256 + threadIdx.x;
        int o = idx >> 8, i = idx & 255;
        const float* p = sr_w + ((size_t)(o * 256 + i)) * 16;
#pragma unroll
        for (int rr = 0; rr < 16; rr++)
            wsrB[(size_t)o * 4096 + rr * 256 + i] = __float2half_rn(p[rr]);
    }
}

// ---------------------------------------------------------------------------
// Split-K(8) reduce + bias + LayerNorm -> src (fp16). grid 256, 256 thr.
// ---------------------------------------------------------------------------
__global__ void reduce_ln(const __half* __restrict__ part, const float* __restrict__ bias,
                          const float* __restrict__ g, const float* __restrict__ bb,
                          __half* __restrict__ out) {
    int lane = threadIdx.x & 31, w = threadIdx.x >> 5;
    int row = blockIdx.x * 8 + w;
    float v[8];
#pragma unroll
    for (int j = 0; j < 8; j++) {
        int c = lane + j * 32;
        float s = 0.f;
#pragma unroll
        for (int ks = 0; ks < 8; ks++)
            s += __half2float(part[((size_t)ks * 2048 + row) * 256 + c]);
        v[j] = s + bias[c];
    }
    float sum = 0.f;
#pragma unroll
    for (int j = 0; j < 8; j++) sum += v[j];
#pragma unroll
    for (int o = 16; o; o >>= 1) sum += __shfl_xor_sync(0xffffffffu, sum, o);
    float mean = sum * (1.f / 256.f);
    float ss = 0.f;
#pragma unroll
    for (int j = 0; j < 8; j++) { float d = v[j] - mean; ss += d * d; }
#pragma unroll
    for (int o = 16; o; o >>= 1) ss += __shfl_xor_sync(0xffffffffu, ss, o);
    float inv = rsqrtf(ss * (1.f / 256.f) + EPS_LN);
#pragma unroll
    for (int j = 0; j < 8; j++) {
        int c = lane + j * 32;
        out[(size_t)row * 256 + c] = __float2half_rn((v[j] - mean) * inv * g[c] + bb[c]);
    }
}

// ---------------------------------------------------------------------------
// fp16 mma GEMM, BK=64, 2-stage double buffer (R13 schedule).
// NB=128: 256 thr, warps 4x2, 2 CTAs/SM. NB=256: 512 thr, warps 4x4, 1 CTA/SM.
// EPI: 0 plain, 1 elu+1, 2 relu, 3 LN, 4 LN+resid, 5 fused attention
// ---------------------------------------------------------------------------
#define EPI_PLAIN    0
#define EPI_ELU1     1
#define EPI_RELU     2
#define EPI_LN       3
#define EPI_LN_RESID 4
#define EPI_ATTN     5

#define RSTRIDE_H 72
#define A_ROWS    128

__host__ __device__ constexpr int stage_halfs(int NB) { return (128 + NB) * RSTRIDE_H; }
__host__ __device__ constexpr int nthreads(int NB) { return NB == 256 ? 512 : 256; }
__host__ __device__ constexpr int smem_req(int NB, int EPI) {
    int mainloop = 2 * stage_halfs(NB) * 2;
    int epi = (128 * (NB + 4) + 256) * 4;
    if (EPI == EPI_ATTN) epi = (128 * (NB + 4) + 512 + 128 + 4096) * 4;
    return mainloop > epi ? mainloop : epi;
}

template <int EPI, int MODE, int NB, bool OUTH>
__global__ __launch_bounds__(nthreads(NB), (NB == 128 ? 2 : 1))
void mma_gemm(const __half* __restrict__ A0, const __half* __restrict__ A1,
              const __half* __restrict__ Bw, void* __restrict__ Cv,
              int Kloc, int KB, int Ntot,
              const float* __restrict__ gamma, const float* __restrict__ beta,
              const float* __restrict__ resid,
              const __half* __restrict__ Bw2, void* __restrict__ C2v) {
    extern __shared__ __half dsm_h[];

    constexpr int NTH   = nthreads(NB);
    constexpr int WM    = 4;                       // warps along M (both paths)
    constexpr int MROWS = 32;                      // rows per warp
    constexpr int MF    = 2;                       // 16-row frags per warp
    constexpr int AP    = 1024 / NTH;              // A uint4 per thread
    constexpr int BLD   = (NB * 8) / NTH;          // B uint4 per thread (=4)
    constexpr int STAGE = stage_halfs(NB);
    constexpr int EPIST = NB + 4;

    const int tid  = threadIdx.x;
    const int lane = tid & 31;
    const int wid  = tid >> 5;
    const int g    = lane >> 2;
    const int t    = lane & 3;
    const int warp_m = wid % WM;
    const int warp_n = wid / WM;

    const int mtile = blockIdx.x * 128;
    int ncol0 = blockIdx.y * NB, kstart = 0;
    const __half* Bsrc = Bw;
    void* Cout = Cv;
    size_t coff = 0;
    if (MODE == 2) { kstart = blockIdx.z * 512; coff = (size_t)blockIdx.z * 2048 * 256; }
    if (MODE == 3) { if (blockIdx.z) { Bsrc = Bw2; Cout = C2v; } }
    const int KT = Kloc / 64;

    float acc[MF][8][4];
#pragma unroll
    for (int i = 0; i < MF; i++)
#pragma unroll
        for (int j = 0; j < 8; j++)
#pragma unroll
            for (int q = 0; q < 4; q++) acc[i][j][q] = 0.f;

    uint4 rA[AP], rB[BLD];

    auto ldg_tile = [&](int kt) {
        const int kbase = kstart + kt * 64;
#pragma unroll
        for (int p = 0; p < AP; p++) {
            int idx = p * NTH + tid;
            int m = idx >> 3, c = idx & 7;
            int kk = kbase + c * 8;
            const __half* gp;
            if (MODE == 2) {
                int mg = mtile + m;
                int b = mg >> 8, s5 = mg & 255;
                int rr = kk >> 8, i = kk & 255;
                int n = (((s5 >> 4) * 4 + (rr >> 2)) << 6) + ((s5 & 15) << 2) + (rr & 3);
                gp = A0 + (((size_t)b << 12) + n) * 256 + i;
            } else if (MODE == 1) {
                gp = (kk < 256) ? (A0 + (size_t)(mtile + m) * 256 + kk)
                                : (A1 + (size_t)(mtile + m) * 256 + (kk - 256));
            } else {
                gp = A0 + (size_t)(mtile + m) * Kloc + kk;
            }
            rA[p] = *(const uint4*)gp;
        }
#pragma unroll
        for (int p = 0; p < BLD; p++) {
            int idx = p * NTH + tid;
            int n = idx >> 3, c = idx & 7;
            rB[p] = *(const uint4*)(Bsrc + (size_t)(ncol0 + n) * KB + kbase + c * 8);
        }
    };
    auto sts_tile = [&](int s) {
        __half* sA = dsm_h + s * STAGE;
        __half* sB = sA + A_ROWS * RSTRIDE_H;
#pragma unroll
        for (int p = 0; p < AP; p++) {
            int idx = p * NTH + tid;
            int m = idx >> 3, c = idx & 7;
            *(uint4*)&sA[m * RSTRIDE_H + c * 8] = rA[p];
        }
#pragma unroll
        for (int p = 0; p < BLD; p++) {
            int idx = p * NTH + tid;
            int n = idx >> 3, c = idx & 7;
            *(uint4*)&sB[n * RSTRIDE_H + c * 8] = rB[p];
        }
    };

    const uint32_t smb = smem_u32(dsm_h);
    const uint32_t a_l = ((warp_m * MROWS + (lane & 7) + ((lane >> 3) & 1) * 8) * RSTRIDE_H
                          + ((lane >> 4) & 1) * 8) * 2;
    const uint32_t b_l = ((A_ROWS + warp_n * 64 + (lane & 7) + ((lane >> 4) & 1) * 8) * RSTRIDE_H
                          + ((lane >> 3) & 1) * 8) * 2;

    ldg_tile(0);
    sts_tile(0);
    if (KT > 1) ldg_tile(1);
    __syncthreads();

    for (int kt = 0; kt < KT; kt++) {
        if (kt + 1 < KT) {
            sts_tile((kt + 1) & 1);
            if (kt + 2 < KT) ldg_tile(kt + 2);
            __syncthreads();
        }
        const uint32_t sbase = smb + (uint32_t)(kt & 1) * (STAGE * 2);
#pragma unroll
        for (int ks = 0; ks < 4; ks++) {
            const uint32_t koffB = ks * 32;
            uint32_t a[MF][4], b[8][2];
#pragma unroll
            for (int mf = 0; mf < MF; mf++)
                ldsm_x4(a[mf][0], a[mf][1], a[mf][2], a[mf][3],
                        sbase + a_l + mf * (16 * RSTRIDE_H * 2) + koffB);
#pragma unroll
            for (int p = 0; p < 4; p++)
                ldsm_x4(b[2 * p][0], b[2 * p][1], b[2 * p + 1][0], b[2 * p + 1][1],
                        sbase + b_l + p * (16 * RSTRIDE_H * 2) + koffB);
#pragma unroll
            for (int mf = 0; mf < MF; mf++)
#pragma unroll
                for (int nf = 0; nf < 8; nf++)
                    mma16(acc[mf][nf], a[mf], b[nf]);
        }
        __syncthreads();
    }

    // ---- epilogue ----
    float* sepi   = (float*)dsm_h;
    float* s_mean = sepi + 128 * EPIST;
    float* s_inv  = s_mean + 128;
    float* z_s    = sepi + 128 * EPIST;
    float* ksum_s = z_s + 512;
    float* kv_s   = ksum_s + 128;
    const bool doAct = (MODE != 3) || (blockIdx.z == 0);

    if (EPI == EPI_ATTN) {
        const int b = mtile >> 12;
        const int H0 = blockIdx.y * 4;
        const float4* kvg = (const float4*)(gamma + (((size_t)(b * 8 + H0)) * 32) * 32);
#pragma unroll
        for (int p = 0; p < 4; p++)
            *(float4*)&kv_s[(p * 256 + tid) * 4] = kvg[p * 256 + tid];
        if (tid < 32)
            *(float4*)&ksum_s[tid * 4] = *(const float4*)(beta + b * 256 + H0 * 32 + tid * 4);
    }

#pragma unroll
    for (int mf = 0; mf < MF; mf++) {
        int r0 = warp_m * MROWS + mf * 16 + g;
#pragma unroll
        for (int nf = 0; nf < 8; nf++) {
            int c0 = warp_n * 64 + nf * 8 + 2 * t;
            float v0 = acc[mf][nf][0], v1 = acc[mf][nf][1];
            float v2 = acc[mf][nf][2], v3 = acc[mf][nf][3];
            if ((EPI == EPI_ELU1 || EPI == EPI_ATTN) && doAct) {
                v0 = (v0 > 0.f) ? v0 + 1.f : __expf(v0);
                v1 = (v1 > 0.f) ? v1 + 1.f : __expf(v1);
                v2 = (v2 > 0.f) ? v2 + 1.f : __expf(v2);
                v3 = (v3 > 0.f) ? v3 + 1.f : __expf(v3);
            }
            if (EPI == EPI_RELU) {
                v0 = fmaxf(v0, 0.f); v1 = fmaxf(v1, 0.f);
                v2 = fmaxf(v2, 0.f); v3 = fmaxf(v3, 0.f);
            }
            *(float2*)&sepi[r0 * EPIST + c0]       = make_float2(v0, v1);
            *(float2*)&sepi[(r0 + 8) * EPIST + c0] = make_float2(v2, v3);
        }
    }
    __syncthreads();

    if (EPI == EPI_ATTN) {
#pragma unroll
        for (int i = 0; i < 2; i++) {
            int p = tid * 2 + i;
            int row = p >> 2, hh = p & 3;
            const float4* qp = (const float4*)&sepi[row * EPIST + hh * 32];
            const float4* kp = (const float4*)&ksum_s[hh * 32];
            float z = 0.f;
#pragma unroll
            for (int q4 = 0; q4 < 8; q4++) {
                float4 qv = qp[q4], kv4 = kp[q4];
                z += qv.x * kv4.x + qv.y * kv4.y + qv.z * kv4.z + qv.w * kv4.w;
            }
            z_s[p] = 1.f / (z + EPS_ATT);
        }
        __syncthreads();

        const int c  = tid & 31;
        const int hf = (tid >> 5) & 1;
        const int hh = tid >> 6;
        float kvr[32];
#pragma unroll
        for (int d = 0; d < 32; d++) kvr[d] = kv_s[hh * 1024 + d * 32 + c];
        __half* msgp = (__half*)Cout;
        const int colg = blockIdx.y * 128 + hh * 32 + c;
#pragma unroll 2
        for (int r = 0; r < 64; r++) {
            int row = hf * 64 + r;
            const float4* qp = (const float4*)&sepi[row * EPIST + hh * 32];
            float m = 0.f;
#pragma unroll
            for (int q4 = 0; q4 < 8; q4++) {
                float4 qv = qp[q4];
                m += qv.x * kvr[q4 * 4] + qv.y * kvr[q4 * 4 + 1]
                   + qv.z * kvr[q4 * 4 + 2] + qv.w * kvr[q4 * 4 + 3];
            }
            m *= z_s[row * 4 + hh];
            msgp[(size_t)(mtile + row) * 256 + colg] = __float2half_rn(m);
        }
        return;
    }

    if ((EPI == EPI_LN || EPI == EPI_LN_RESID) && tid < 128) {
        const float* rowp = sepi + tid * EPIST;
        float sum = 0.f, ss = 0.f;
#pragma unroll 8
        for (int j = 0; j < NB / 4; j++) {
            float4 v = *(const float4*)&rowp[j * 4];
            sum += v.x + v.y + v.z + v.w;
            ss  += v.x * v.x + v.y * v.y + v.z * v.z + v.w * v.w;
        }
        float mean = sum * (1.f / 256.f);
        float var  = ss * (1.f / 256.f) - mean * mean;
        s_mean[tid] = mean;
        s_inv[tid]  = rsqrtf(var + EPS_LN);
    }
    if (EPI == EPI_LN || EPI == EPI_LN_RESID) __syncthreads();

#pragma unroll 4
    for (int p = 0; p < (128 * NB / 4) / NTH; p++) {
        int idx4 = p * NTH + tid;
        int row = idx4 / (NB / 4);
        int c4  = (idx4 % (NB / 4)) << 2;
        float4 v = *(const float4*)&sepi[row * EPIST + c4];
        if (EPI == EPI_LN || EPI == EPI_LN_RESID) {
            float m = s_mean[row], iv = s_inv[row];
            float4 gm = *(const float4*)&gamma[c4];
            float4 bt = *(const float4*)&beta[c4];
            v.x = (v.x - m) * iv * gm.x + bt.x;
            v.y = (v.y - m) * iv * gm.y + bt.y;
            v.z = (v.z - m) * iv * gm.z + bt.z;
            v.w = (v.w - m) * iv * gm.w + bt.w;
            if (EPI == EPI_LN_RESID) {
                float4 r = *(const float4*)&resid[(size_t)(mtile + row) * 256 + c4];
                v.x += r.x; v.y += r.y; v.z += r.z; v.w += r.w;
            }
        }
        size_t off = coff + (size_t)(mtile + row) * Ntot + ncol0 + c4;
        if (OUTH) {
            __half2 h0 = __floats2half2_rn(v.x, v.y);
            __half2 h1 = __floats2half2_rn(v.z, v.w);
            *(uint2*)&((__half*)Cout)[off] = make_uint2(h2u(h0), h2u(h1));
        } else {
            *(float4*)&((float*)Cout)[off] = v;
        }
    }
}

// ---------------------------------------------------------------------------
// KV = sum_s K^T V, Ksum = sum_s K. fp16 in, fp32 math. grid 64, 256 thr.
// ---------------------------------------------------------------------------
__global__ void kv_kernel(const __half* __restrict__ kmat, const __half* __restrict__ vmat,
                          float* __restrict__ kv, float* __restrict__ ksum) {
    __shared__ float Ks[128][32];
    __shared__ float Vs[128][32];
    int bh = blockIdx.x, b = bh >> 3, h = bh & 7;
    int tid = threadIdx.x;
    int d = tid & 31, vg = tid >> 5;
    float acc0 = 0.f, acc1 = 0.f, acc2 = 0.f, acc3 = 0.f, ka = 0.f;

    for (int ch = 0; ch < 2; ch++) {
        int sl = tid >> 3, c4 = tid & 7;
#pragma unroll
        for (int ss = 0; ss < 4; ss++) {
            int srow = ch * 128 + ss * 32 + sl;
            size_t base = ((size_t)(b * 256 + srow)) * 256 + h * 32 + c4 * 4;
            uint2 kw = *(const uint2*)&kmat[base];
            uint2 vw = *(const uint2*)&vmat[base];
            __half2* kh = (__half2*)&kw;
            __half2* vh = (__half2*)&vw;
            float2 k0 = __half22float2(kh[0]), k1 = __half22float2(kh[1]);
            float2 w0 = __half22float2(vh[0]), w1 = __half22float2(vh[1]);
            Ks[ss * 32 + sl][c4 * 4 + 0] = k0.x; Ks[ss * 32 + sl][c4 * 4 + 1] = k0.y;
            Ks[ss * 32 + sl][c4 * 4 + 2] = k1.x; Ks[ss * 32 + sl][c4 * 4 + 3] = k1.y;
            Vs[ss * 32 + sl][c4 * 4 + 0] = w0.x; Vs[ss * 32 + sl][c4 * 4 + 1] = w0.y;
            Vs[ss * 32 + sl][c4 * 4 + 2] = w1.x; Vs[ss * 32 + sl][c4 * 4 + 3] = w1.y;
        }
        __syncthreads();
#pragma unroll 4
        for (int s = 0; s < 128; s++) {
            float kd = Ks[s][d];
            float4 vv = *(float4*)&Vs[s][vg * 4];
            acc0 += kd * vv.x; acc1 += kd * vv.y;
            acc2 += kd * vv.z; acc3 += kd * vv.w;
            if (vg == 0) ka += kd;
        }
        __syncthreads();
    }
    float* kvp = kv + ((size_t)bh * 32 + d) * 32 + vg * 4;
    kvp[0] = acc0; kvp[1] = acc1; kvp[2] = acc2; kvp[3] = acc3;
    if (vg == 0) ksum[bh * 32 + d] = ka;
}

// ---------------------------------------------------------------------------
// Launch
// ---------------------------------------------------------------------------
extern "C" void kernel_launch(void* const* d_in, const int* in_sizes, int n_in,
                              void* d_out, int out_size) {
    const float* x      = (const float*)d_in[0];
    const float* sr_w   = (const float*)d_in[1];
    const float* sr_b   = (const float*)d_in[2];
    const float* norm_g = (const float*)d_in[3];
    const float* norm_b = (const float*)d_in[4];
    const float* wq     = (const float*)d_in[5];
    const float* wk     = (const float*)d_in[6];
    const float* wv     = (const float*)d_in[7];
    const float* wm     = (const float*)d_in[8];
    const float* w1     = (const float*)d_in[9];
    const float* w2     = (const float*)d_in[10];
    const float* n1g    = (const float*)d_in[11];
    const float* n1b    = (const float*)d_in[12];
    const float* n2g    = (const float*)d_in[13];
    const float* n2b    = (const float*)d_in[14];
    float* out = (float*)d_out;

    __half *wsrB, *wqr, *wkr, *wvr, *wmr, *w1r, *w2r;
    __half *xh, *part, *src, *kmat, *vmat, *msg, *msgn, *hmid;
    float *kvp, *ksump;
    cudaGetSymbolAddress((void**)&wsrB, g_wsrB);
    cudaGetSymbolAddress((void**)&wqr,  g_wqr);
    cudaGetSymbolAddress((void**)&wkr,  g_wkr);
    cudaGetSymbolAddress((void**)&wvr,  g_wvr);
    cudaGetSymbolAddress((void**)&wmr,  g_wmr);
    cudaGetSymbolAddress((void**)&w1r,  g_w1r);
    cudaGetSymbolAddress((void**)&w2r,  g_w2r);
    cudaGetSymbolAddress((void**)&xh,   g_xh);
    cudaGetSymbolAddress((void**)&part, g_part);
    cudaGetSymbolAddress((void**)&src,  g_src);
    cudaGetSymbolAddress((void**)&kmat, g_kmat);
    cudaGetSymbolAddress((void**)&vmat, g_vmat);
    cudaGetSymbolAddress((void**)&kvp,  g_kv);
    cudaGetSymbolAddress((void**)&ksump,g_ksum);
    cudaGetSymbolAddress((void**)&msg,  g_msg);
    cudaGetSymbolAddress((void**)&msgn, g_msgn);
    cudaGetSymbolAddress((void**)&hmid, g_hmid);

    constexpr int SM128  = smem_req(128, EPI_PLAIN);
    constexpr int SMATTN = smem_req(128, EPI_ATTN);
    constexpr int SM256  = smem_req(256, EPI_LN);
    cudaFuncSetAttribute(mma_gemm<EPI_PLAIN, 2, 128, true>,    cudaFuncAttributeMaxDynamicSharedMemorySize, SM128);
    cudaFuncSetAttribute(mma_gemm<EPI_ELU1, 3, 128, true>,     cudaFuncAttributeMaxDynamicSharedMemorySize, SM128);
    cudaFuncSetAttribute(mma_gemm<EPI_ATTN, 0, 128, true>,     cudaFuncAttributeMaxDynamicSharedMemorySize, SMATTN);
    cudaFuncSetAttribute(mma_gemm<EPI_RELU, 1, 128, true>,     cudaFuncAttributeMaxDynamicSharedMemorySize, SM128);
    cudaFuncSetAttribute(mma_gemm<EPI_LN, 0, 256, true>,       cudaFuncAttributeMaxDynamicSharedMemorySize, SM256);
    cudaFuncSetAttribute(mma_gemm<EPI_LN_RESID, 0, 256, false>,cudaFuncAttributeMaxDynamicSharedMemorySize, SM256);

    prep_all<<<11008, 256>>>(x, sr_w, wq, wk, wv, wm, w1, w2,
                             xh, wsrB, wqr, wkr, wvr, wmr, w1r, w2r);

    // conv-as-GEMM (split-K=8 on z) + reduce/bias/LN -> src
    mma_gemm<EPI_PLAIN, 2, 128, true><<<dim3(16, 2, 8), 256, SM128>>>(
        xh, nullptr, wsrB, part, 512, 4096, 256, nullptr, nullptr, nullptr, nullptr, nullptr);
    reduce_ln<<<256, 256>>>(part, sr_b, norm_g, norm_b, src);

    // fused k/v projections (M=2048)
    mma_gemm<EPI_ELU1, 3, 128, true><<<dim3(16, 2, 2), 256, SM128>>>(
        src, nullptr, wkr, kmat, 256, 256, 256, nullptr, nullptr, nullptr, wvr, vmat);

    kv_kernel<<<64, 256>>>(kmat, vmat, kvp, ksump);

    // q projection + fused linear attention -> msg
    mma_gemm<EPI_ATTN, 0, 128, true><<<dim3(256, 2), 256, SMATTN>>>(
        xh, nullptr, wqr, msg, 256, 256, 256, kvp, ksump, nullptr, nullptr, nullptr);

    // merge projection + LN1 (NB=256, 512 threads)
    mma_gemm<EPI_LN, 0, 256, true><<<dim3(256, 1), 512, SM256>>>(
        msg, nullptr, wmr, msgn, 256, 256, 256, n1g, n1b, nullptr, nullptr, nullptr);

    // MLP1: concat(xh, msgn) @ w1^T -> relu
    mma_gemm<EPI_RELU, 1, 128, true><<<dim3(256, 4), 256, SM128>>>(
        xh, msgn, w1r, hmid, 512, 512, 512, nullptr, nullptr, nullptr, nullptr, nullptr);

    // MLP2 + LN2 + residual -> out (NB=256, 512 threads, fp32 out)
    mma_gemm<EPI_LN_RESID, 0, 256, false><<<dim3(256, 1), 512, SM256>>>(
        hmid, nullptr, w2r, out, 512, 512, 256, n2g, n2b, x, nullptr, nullptr);
}

// round 17
// speedup vs baseline: 1.3442x; 1.0389x over previous
#include <cuda_runtime.h>
#include <cuda_fp16.h>
#include <math.h>
#include <stdint.h>

#define EPS_LN  1e-5f
#define EPS_ATT 1e-6f

// ---------------------------------------------------------------------------
// helpers
// ---------------------------------------------------------------------------
__device__ __forceinline__ uint32_t smem_u32(const void* p) {
    uint32_t a;
    asm("{ .reg .u64 t; cvta.to.shared.u64 t, %1; cvt.u32.u64 %0, t; }" : "=r"(a) : "l"(p));
    return a;
}
__device__ __forceinline__ void mma16(float* c, const uint32_t* a, const uint32_t* b) {
    asm volatile(
        "mma.sync.aligned.m16n8k16.row.col.f32.f16.f16.f32 "
        "{%0,%1,%2,%3}, {%4,%5,%6,%7}, {%8,%9}, {%0,%1,%2,%3};"
        : "+f"(c[0]), "+f"(c[1]), "+f"(c[2]), "+f"(c[3])
        : "r"(a[0]), "r"(a[1]), "r"(a[2]), "r"(a[3]), "r"(b[0]), "r"(b[1]));
}
__device__ __forceinline__ void ldsm_x4(uint32_t& r0, uint32_t& r1, uint32_t& r2, uint32_t& r3,
                                        uint32_t addr) {
    asm volatile("ldmatrix.sync.aligned.m8n8.x4.shared.b16 {%0,%1,%2,%3}, [%4];"
        : "=r"(r0), "=r"(r1), "=r"(r2), "=r"(r3) : "r"(addr));
}
__device__ __forceinline__ uint32_t h2u(__half2 h) { return *(uint32_t*)&h; }

// ---------------------------------------------------------------------------
// Scratch
// ---------------------------------------------------------------------------
__device__ __half g_wsrB[256 * 4096];
__device__ __half g_wqr [256 * 256];
__device__ __half g_wkr [256 * 256];
__device__ __half g_wvr [256 * 256];
__device__ __half g_wmr [256 * 256];
__device__ __half g_w1r [512 * 512];
__device__ __half g_w2r [256 * 512];
__device__ __half g_xh  [8 * 4096 * 256];
__device__ __half g_part[8 * 2048 * 256];
__device__ __half g_src [2048 * 256];
__device__ __half g_kmat[2048 * 256];
__device__ __half g_vmat[2048 * 256];
__device__ float  g_kv  [64 * 32 * 32];
__device__ float  g_ksum[64 * 32];
__device__ __half g_msg [8 * 4096 * 256];
__device__ __half g_msgn[8 * 4096 * 256];
__device__ __half g_hmid[8 * 4096 * 512];

// ---------------------------------------------------------------------------
// Unified prep. grid 11008 x 256.
// ---------------------------------------------------------------------------
__global__ void prep_all(const float* __restrict__ x,
                         const float* __restrict__ sr_w,
                         const float* __restrict__ wq, const float* __restrict__ wk,
                         const float* __restrict__ wv, const float* __restrict__ wm,
                         const float* __restrict__ w1, const float* __restrict__ w2,
                         __half* __restrict__ xh, __half* __restrict__ wsrB,
                         __half* __restrict__ oq, __half* __restrict__ ok,
                         __half* __restrict__ ov, __half* __restrict__ om,
                         __half* __restrict__ o1, __half* __restrict__ o2) {
    int bid = blockIdx.x;
    if (bid < 8192) {
        size_t i = ((size_t)bid * 256 + threadIdx.x) * 4;
        float4 v = *(const float4*)&x[i];
        __half2 h0 = __floats2half2_rn(v.x, v.y);
        __half2 h1 = __floats2half2_rn(v.z, v.w);
        *(uint2*)&xh[i] = make_uint2(h2u(h0), h2u(h1));
        return;
    }
    bid -= 8192;
    if (bid < 2560) {
        const float* src; __half* dst; int base;
        if      (bid < 256)  { src = wq; dst = oq; base = 0; }
        else if (bid < 512)  { src = wk; dst = ok; base = 256; }
        else if (bid < 768)  { src = wv; dst = ov; base = 512; }
        else if (bid < 1024) { src = wm; dst = om; base = 768; }
        else if (bid < 2048) { src = w1; dst = o1; base = 1024; }
        else                 { src = w2; dst = o2; base = 2048; }
        int idx = (bid - base) * 256 + threadIdx.x;
        dst[idx] = __float2half_rn(src[idx]);
        return;
    }
    bid -= 2560;
    {
        int idx = bid * 256 + threadIdx.x;
        int o = idx >> 8, i = idx & 255;
        const float* p = sr_w + ((size_t)(o * 256 + i)) * 16;
#pragma unroll
        for (int rr = 0; rr < 16; rr++)
            wsrB[(size_t)o * 4096 + rr * 256 + i] = __float2half_rn(p[rr]);
    }
}

// ---------------------------------------------------------------------------
// Split-K(8) reduce + bias + LayerNorm -> src (fp16). grid 256, 256 thr.
// ---------------------------------------------------------------------------
__global__ void reduce_ln(const __half* __restrict__ part, const float* __restrict__ bias,
                          const float* __restrict__ g, const float* __restrict__ bb,
                          __half* __restrict__ out) {
    int lane = threadIdx.x & 31, w = threadIdx.x >> 5;
    int row = blockIdx.x * 8 + w;
    float v[8];
#pragma unroll
    for (int j = 0; j < 8; j++) {
        int c = lane + j * 32;
        float s = 0.f;
#pragma unroll
        for (int ks = 0; ks < 8; ks++)
            s += __half2float(part[((size_t)ks * 2048 + row) * 256 + c]);
        v[j] = s + bias[c];
    }
    float sum = 0.f;
#pragma unroll
    for (int j = 0; j < 8; j++) sum += v[j];
#pragma unroll
    for (int o = 16; o; o >>= 1) sum += __shfl_xor_sync(0xffffffffu, sum, o);
    float mean = sum * (1.f / 256.f);
    float ss = 0.f;
#pragma unroll
    for (int j = 0; j < 8; j++) { float d = v[j] - mean; ss += d * d; }
#pragma unroll
    for (int o = 16; o; o >>= 1) ss += __shfl_xor_sync(0xffffffffu, ss, o);
    float inv = rsqrtf(ss * (1.f / 256.f) + EPS_LN);
#pragma unroll
    for (int j = 0; j < 8; j++) {
        int c = lane + j * 32;
        out[(size_t)row * 256 + c] = __float2half_rn((v[j] - mean) * inv * g[c] + bb[c]);
    }
}

// ---------------------------------------------------------------------------
// fp16 mma GEMM, BK=64, compile-time KTT stages, fully unrolled mainloop.
// NB=128: 256 thr, 2 CTAs/SM. NB=256: 512 thr, 1 CTA/SM. R13 barrier schedule.
// EPI: 0 plain, 1 elu+1, 2 relu, 3 LN, 4 LN+resid, 5 fused attention
// ---------------------------------------------------------------------------
#define EPI_PLAIN    0
#define EPI_ELU1     1
#define EPI_RELU     2
#define EPI_LN       3
#define EPI_LN_RESID 4
#define EPI_ATTN     5

#define RSTRIDE_H 72
#define A_ROWS    128

__host__ __device__ constexpr int stage_halfs(int NB) { return (128 + NB) * RSTRIDE_H; }
__host__ __device__ constexpr int nthreads(int NB) { return NB == 256 ? 512 : 256; }
__host__ __device__ constexpr int smem_req(int NB, int EPI) {
    int mainloop = 2 * stage_halfs(NB) * 2;
    int epi = (128 * (NB + 4) + 256) * 4;
    if (EPI == EPI_ATTN) epi = (128 * (NB + 4) + 512 + 128 + 4096) * 4;
    return mainloop > epi ? mainloop : epi;
}

template <int EPI, int MODE, int NB, bool OUTH, int KTT>
__global__ __launch_bounds__(nthreads(NB), (NB == 128 ? 2 : 1))
void mma_gemm(const __half* __restrict__ A0, const __half* __restrict__ A1,
              const __half* __restrict__ Bw, void* __restrict__ Cv,
              int KB, int Ntot,
              const float* __restrict__ gamma, const float* __restrict__ beta,
              const float* __restrict__ resid,
              const __half* __restrict__ Bw2, void* __restrict__ C2v) {
    extern __shared__ __half dsm_h[];

    constexpr int NTH   = nthreads(NB);
    constexpr int WM    = 4;
    constexpr int MROWS = 32;
    constexpr int MF    = 2;
    constexpr int AP    = 1024 / NTH;
    constexpr int BLD   = (NB * 8) / NTH;
    constexpr int STAGE = stage_halfs(NB);
    constexpr int EPIST = NB + 4;
    constexpr int KLOC  = KTT * 64;      // A row stride for MODE 0

    const int tid  = threadIdx.x;
    const int lane = tid & 31;
    const int wid  = tid >> 5;
    const int g    = lane >> 2;
    const int t    = lane & 3;
    const int warp_m = wid % WM;
    const int warp_n = wid / WM;

    const int mtile = blockIdx.x * 128;
    int ncol0 = blockIdx.y * NB, kstart = 0;
    const __half* Bsrc = Bw;
    void* Cout = Cv;
    size_t coff = 0;
    if (MODE == 2) { kstart = blockIdx.z * 512; coff = (size_t)blockIdx.z * 2048 * 256; }
    if (MODE == 3) { if (blockIdx.z) { Bsrc = Bw2; Cout = C2v; } }

    float acc[MF][8][4];
#pragma unroll
    for (int i = 0; i < MF; i++)
#pragma unroll
        for (int j = 0; j < 8; j++)
#pragma unroll
            for (int q = 0; q < 4; q++) acc[i][j][q] = 0.f;

    uint4 rA[AP], rB[BLD];

    auto ldg_tile = [&](int kt) {
        const int kbase = kstart + kt * 64;
#pragma unroll
        for (int p = 0; p < AP; p++) {
            int idx = p * NTH + tid;
            int m = idx >> 3, c = idx & 7;
            int kk = kbase + c * 8;
            const __half* gp;
            if (MODE == 2) {
                int mg = mtile + m;
                int b = mg >> 8, s5 = mg & 255;
                int rr = kk >> 8, i = kk & 255;
                int n = (((s5 >> 4) * 4 + (rr >> 2)) << 6) + ((s5 & 15) << 2) + (rr & 3);
                gp = A0 + (((size_t)b << 12) + n) * 256 + i;
            } else if (MODE == 1) {
                gp = (kk < 256) ? (A0 + (size_t)(mtile + m) * 256 + kk)
                                : (A1 + (size_t)(mtile + m) * 256 + (kk - 256));
            } else {
                gp = A0 + (size_t)(mtile + m) * KLOC + kk;
            }
            rA[p] = *(const uint4*)gp;
        }
#pragma unroll
        for (int p = 0; p < BLD; p++) {
            int idx = p * NTH + tid;
            int n = idx >> 3, c = idx & 7;
            rB[p] = *(const uint4*)(Bsrc + (size_t)(ncol0 + n) * KB + kbase + c * 8);
        }
    };
    auto sts_tile = [&](int s) {
        __half* sA = dsm_h + s * STAGE;
        __half* sB = sA + A_ROWS * RSTRIDE_H;
#pragma unroll
        for (int p = 0; p < AP; p++) {
            int idx = p * NTH + tid;
            int m = idx >> 3, c = idx & 7;
            *(uint4*)&sA[m * RSTRIDE_H + c * 8] = rA[p];
        }
#pragma unroll
        for (int p = 0; p < BLD; p++) {
            int idx = p * NTH + tid;
            int n = idx >> 3, c = idx & 7;
            *(uint4*)&sB[n * RSTRIDE_H + c * 8] = rB[p];
        }
    };

    const uint32_t smb = smem_u32(dsm_h);
    const uint32_t a_l = ((warp_m * MROWS + (lane & 7) + ((lane >> 3) & 1) * 8) * RSTRIDE_H
                          + ((lane >> 4) & 1) * 8) * 2;
    const uint32_t b_l = ((A_ROWS + warp_n * 64 + (lane & 7) + ((lane >> 4) & 1) * 8) * RSTRIDE_H
                          + ((lane >> 3) & 1) * 8) * 2;

    ldg_tile(0);
    sts_tile(0);
    if (KTT > 1) ldg_tile(1);
    __syncthreads();

#pragma unroll
    for (int kt = 0; kt < KTT; kt++) {
        if (kt + 1 < KTT) {
            sts_tile((kt + 1) & 1);
            if (kt + 2 < KTT) ldg_tile(kt + 2);
            __syncthreads();
        }
        const uint32_t sbase = smb + (uint32_t)(kt & 1) * (STAGE * 2);
#pragma unroll
        for (int ks = 0; ks < 4; ks++) {
            const uint32_t koffB = ks * 32;
            uint32_t a[MF][4], b[8][2];
#pragma unroll
            for (int mf = 0; mf < MF; mf++)
                ldsm_x4(a[mf][0], a[mf][1], a[mf][2], a[mf][3],
                        sbase + a_l + mf * (16 * RSTRIDE_H * 2) + koffB);
#pragma unroll
            for (int p = 0; p < 4; p++)
                ldsm_x4(b[2 * p][0], b[2 * p][1], b[2 * p + 1][0], b[2 * p + 1][1],
                        sbase + b_l + p * (16 * RSTRIDE_H * 2) + koffB);
#pragma unroll
            for (int mf = 0; mf < MF; mf++)
#pragma unroll
                for (int nf = 0; nf < 8; nf++)
                    mma16(acc[mf][nf], a[mf], b[nf]);
        }
        __syncthreads();
    }

    // ---- epilogue ----
    float* sepi   = (float*)dsm_h;
    float* s_mean = sepi + 128 * EPIST;
    float* s_inv  = s_mean + 128;
    float* z_s    = sepi + 128 * EPIST;
    float* ksum_s = z_s + 512;
    float* kv_s   = ksum_s + 128;
    const bool doAct = (MODE != 3) || (blockIdx.z == 0);

    if (EPI == EPI_ATTN) {
        const int b = mtile >> 12;
        const int H0 = blockIdx.y * 4;
        const float4* kvg = (const float4*)(gamma + (((size_t)(b * 8 + H0)) * 32) * 32);
#pragma unroll
        for (int p = 0; p < 4; p++)
            *(float4*)&kv_s[(p * 256 + tid) * 4] = kvg[p * 256 + tid];
        if (tid < 32)
            *(float4*)&ksum_s[tid * 4] = *(const float4*)(beta + b * 256 + H0 * 32 + tid * 4);
    }

#pragma unroll
    for (int mf = 0; mf < MF; mf++) {
        int r0 = warp_m * MROWS + mf * 16 + g;
#pragma unroll
        for (int nf = 0; nf < 8; nf++) {
            int c0 = warp_n * 64 + nf * 8 + 2 * t;
            float v0 = acc[mf][nf][0], v1 = acc[mf][nf][1];
            float v2 = acc[mf][nf][2], v3 = acc[mf][nf][3];
            if ((EPI == EPI_ELU1 || EPI == EPI_ATTN) && doAct) {
                v0 = (v0 > 0.f) ? v0 + 1.f : __expf(v0);
                v1 = (v1 > 0.f) ? v1 + 1.f : __expf(v1);
                v2 = (v2 > 0.f) ? v2 + 1.f : __expf(v2);
                v3 = (v3 > 0.f) ? v3 + 1.f : __expf(v3);
            }
            if (EPI == EPI_RELU) {
                v0 = fmaxf(v0, 0.f); v1 = fmaxf(v1, 0.f);
                v2 = fmaxf(v2, 0.f); v3 = fmaxf(v3, 0.f);
            }
            *(float2*)&sepi[r0 * EPIST + c0]       = make_float2(v0, v1);
            *(float2*)&sepi[(r0 + 8) * EPIST + c0] = make_float2(v2, v3);
        }
    }
    __syncthreads();

    if (EPI == EPI_ATTN) {
#pragma unroll
        for (int i = 0; i < 2; i++) {
            int p = tid * 2 + i;
            int row = p >> 2, hh = p & 3;
            const float4* qp = (const float4*)&sepi[row * EPIST + hh * 32];
            const float4* kp = (const float4*)&ksum_s[hh * 32];
            float z = 0.f;
#pragma unroll
            for (int q4 = 0; q4 < 8; q4++) {
                float4 qv = qp[q4], kv4 = kp[q4];
                z += qv.x * kv4.x + qv.y * kv4.y + qv.z * kv4.z + qv.w * kv4.w;
            }
            z_s[p] = 1.f / (z + EPS_ATT);
        }
        __syncthreads();

        const int c  = tid & 31;
        const int hf = (tid >> 5) & 1;
        const int hh = tid >> 6;
        float kvr[32];
#pragma unroll
        for (int d = 0; d < 32; d++) kvr[d] = kv_s[hh * 1024 + d * 32 + c];
        __half* msgp = (__half*)Cout;
        const int colg = blockIdx.y * 128 + hh * 32 + c;
#pragma unroll 2
        for (int r = 0; r < 64; r++) {
            int row = hf * 64 + r;
            const float4* qp = (const float4*)&sepi[row * EPIST + hh * 32];
            float m = 0.f;
#pragma unroll
            for (int q4 = 0; q4 < 8; q4++) {
                float4 qv = qp[q4];
                m += qv.x * kvr[q4 * 4] + qv.y * kvr[q4 * 4 + 1]
                   + qv.z * kvr[q4 * 4 + 2] + qv.w * kvr[q4 * 4 + 3];
            }
            m *= z_s[row * 4 + hh];
            msgp[(size_t)(mtile + row) * 256 + colg] = __float2half_rn(m);
        }
        return;
    }

    if ((EPI == EPI_LN || EPI == EPI_LN_RESID) && tid < 128) {
        const float* rowp = sepi + tid * EPIST;
        float sum = 0.f, ss = 0.f;
#pragma unroll 8
        for (int j = 0; j < NB / 4; j++) {
            float4 v = *(const float4*)&rowp[j * 4];
            sum += v.x + v.y + v.z + v.w;
            ss  += v.x * v.x + v.y * v.y + v.z * v.z + v.w * v.w;
        }
        float mean = sum * (1.f / 256.f);
        float var  = ss * (1.f / 256.f) - mean * mean;
        s_mean[tid] = mean;
        s_inv[tid]  = rsqrtf(var + EPS_LN);
    }
    if (EPI == EPI_LN || EPI == EPI_LN_RESID) __syncthreads();

#pragma unroll 4
    for (int p = 0; p < (128 * NB / 4) / NTH; p++) {
        int idx4 = p * NTH + tid;
        int row = idx4 / (NB / 4);
        int c4  = (idx4 % (NB / 4)) << 2;
        float4 v = *(const float4*)&sepi[row * EPIST + c4];
        if (EPI == EPI_LN || EPI == EPI_LN_RESID) {
            float m = s_mean[row], iv = s_inv[row];
            float4 gm = *(const float4*)&gamma[c4];
            float4 bt = *(const float4*)&beta[c4];
            v.x = (v.x - m) * iv * gm.x + bt.x;
            v.y = (v.y - m) * iv * gm.y + bt.y;
            v.z = (v.z - m) * iv * gm.z + bt.z;
            v.w = (v.w - m) * iv * gm.w + bt.w;
            if (EPI == EPI_LN_RESID) {
                float4 r = *(const float4*)&resid[(size_t)(mtile + row) * 256 + c4];
                v.x += r.x; v.y += r.y; v.z += r.z; v.w += r.w;
            }
        }
        size_t off = coff + (size_t)(mtile + row) * Ntot + ncol0 + c4;
        if (OUTH) {
            __half2 h0 = __floats2half2_rn(v.x, v.y);
            __half2 h1 = __floats2half2_rn(v.z, v.w);
            *(uint2*)&((__half*)Cout)[off] = make_uint2(h2u(h0), h2u(h1));
        } else {
            *(float4*)&((float*)Cout)[off] = v;
        }
    }
}

// ---------------------------------------------------------------------------
// KV = sum_s K^T V, Ksum = sum_s K. fp16 in, fp32 math. grid 64, 256 thr.
// ---------------------------------------------------------------------------
__global__ void kv_kernel(const __half* __restrict__ kmat, const __half* __restrict__ vmat,
                          float* __restrict__ kv, float* __restrict__ ksum) {
    __shared__ float Ks[128][32];
    __shared__ float Vs[128][32];
    int bh = blockIdx.x, b = bh >> 3, h = bh & 7;
    int tid = threadIdx.x;
    int d = tid & 31, vg = tid >> 5;
    float acc0 = 0.f, acc1 = 0.f, acc2 = 0.f, acc3 = 0.f, ka = 0.f;

    for (int ch = 0; ch < 2; ch++) {
        int sl = tid >> 3, c4 = tid & 7;
#pragma unroll
        for (int ss = 0; ss < 4; ss++) {
            int srow = ch * 128 + ss * 32 + sl;
            size_t base = ((size_t)(b * 256 + srow)) * 256 + h * 32 + c4 * 4;
            uint2 kw = *(const uint2*)&kmat[base];
            uint2 vw = *(const uint2*)&vmat[base];
            __half2* kh = (__half2*)&kw;
            __half2* vh = (__half2*)&vw;
            float2 k0 = __half22float2(kh[0]), k1 = __half22float2(kh[1]);
            float2 w0 = __half22float2(vh[0]), w1 = __half22float2(vh[1]);
            Ks[ss * 32 + sl][c4 * 4 + 0] = k0.x; Ks[ss * 32 + sl][c4 * 4 + 1] = k0.y;
            Ks[ss * 32 + sl][c4 * 4 + 2] = k1.x; Ks[ss * 32 + sl][c4 * 4 + 3] = k1.y;
            Vs[ss * 32 + sl][c4 * 4 + 0] = w0.x; Vs[ss * 32 + sl][c4 * 4 + 1] = w0.y;
            Vs[ss * 32 + sl][c4 * 4 + 2] = w1.x; Vs[ss * 32 + sl][c4 * 4 + 3] = w1.y;
        }
        __syncthreads();
#pragma unroll 4
        for (int s = 0; s < 128; s++) {
            float kd = Ks[s][d];
            float4 vv = *(float4*)&Vs[s][vg * 4];
            acc0 += kd * vv.x; acc1 += kd * vv.y;
            acc2 += kd * vv.z; acc3 += kd * vv.w;
            if (vg == 0) ka += kd;
        }
        __syncthreads();
    }
    float* kvp = kv + ((size_t)bh * 32 + d) * 32 + vg * 4;
    kvp[0] = acc0; kvp[1] = acc1; kvp[2] = acc2; kvp[3] = acc3;
    if (vg == 0) ksum[bh * 32 + d] = ka;
}

// ---------------------------------------------------------------------------
// Launch
// ---------------------------------------------------------------------------
extern "C" void kernel_launch(void* const* d_in, const int* in_sizes, int n_in,
                              void* d_out, int out_size) {
    const float* x      = (const float*)d_in[0];
    const float* sr_w   = (const float*)d_in[1];
    const float* sr_b   = (const float*)d_in[2];
    const float* norm_g = (const float*)d_in[3];
    const float* norm_b = (const float*)d_in[4];
    const float* wq     = (const float*)d_in[5];
    const float* wk     = (const float*)d_in[6];
    const float* wv     = (const float*)d_in[7];
    const float* wm     = (const float*)d_in[8];
    const float* w1     = (const float*)d_in[9];
    const float* w2     = (const float*)d_in[10];
    const float* n1g    = (const float*)d_in[11];
    const float* n1b    = (const float*)d_in[12];
    const float* n2g    = (const float*)d_in[13];
    const float* n2b    = (const float*)d_in[14];
    float* out = (float*)d_out;

    __half *wsrB, *wqr, *wkr, *wvr, *wmr, *w1r, *w2r;
    __half *xh, *part, *src, *kmat, *vmat, *msg, *msgn, *hmid;
    float *kvp, *ksump;
    cudaGetSymbolAddress((void**)&wsrB, g_wsrB);
    cudaGetSymbolAddress((void**)&wqr,  g_wqr);
    cudaGetSymbolAddress((void**)&wkr,  g_wkr);
    cudaGetSymbolAddress((void**)&wvr,  g_wvr);
    cudaGetSymbolAddress((void**)&wmr,  g_wmr);
    cudaGetSymbolAddress((void**)&w1r,  g_w1r);
    cudaGetSymbolAddress((void**)&w2r,  g_w2r);
    cudaGetSymbolAddress((void**)&xh,   g_xh);
    cudaGetSymbolAddress((void**)&part, g_part);
    cudaGetSymbolAddress((void**)&src,  g_src);
    cudaGetSymbolAddress((void**)&kmat, g_kmat);
    cudaGetSymbolAddress((void**)&vmat, g_vmat);
    cudaGetSymbolAddress((void**)&kvp,  g_kv);
    cudaGetSymbolAddress((void**)&ksump,g_ksum);
    cudaGetSymbolAddress((void**)&msg,  g_msg);
    cudaGetSymbolAddress((void**)&msgn, g_msgn);
    cudaGetSymbolAddress((void**)&hmid, g_hmid);

    constexpr int SM128  = smem_req(128, EPI_PLAIN);
    constexpr int SMATTN = smem_req(128, EPI_ATTN);
    constexpr int SM256  = smem_req(256, EPI_LN);
    cudaFuncSetAttribute(mma_gemm<EPI_PLAIN, 2, 128, true, 8>,    cudaFuncAttributeMaxDynamicSharedMemorySize, SM128);
    cudaFuncSetAttribute(mma_gemm<EPI_ELU1, 3, 128, true, 4>,     cudaFuncAttributeMaxDynamicSharedMemorySize, SM128);
    cudaFuncSetAttribute(mma_gemm<EPI_ATTN, 0, 128, true, 4>,     cudaFuncAttributeMaxDynamicSharedMemorySize, SMATTN);
    cudaFuncSetAttribute(mma_gemm<EPI_RELU, 1, 128, true, 8>,     cudaFuncAttributeMaxDynamicSharedMemorySize, SM128);
    cudaFuncSetAttribute(mma_gemm<EPI_LN, 0, 256, true, 4>,       cudaFuncAttributeMaxDynamicSharedMemorySize, SM256);
    cudaFuncSetAttribute(mma_gemm<EPI_LN_RESID, 0, 256, false, 8>,cudaFuncAttributeMaxDynamicSharedMemorySize, SM256);

    prep_all<<<11008, 256>>>(x, sr_w, wq, wk, wv, wm, w1, w2,
                             xh, wsrB, wqr, wkr, wvr, wmr, w1r, w2r);

    // conv-as-GEMM (split-K=8 on z, KTT=8) + reduce/bias/LN -> src
    mma_gemm<EPI_PLAIN, 2, 128, true, 8><<<dim3(16, 2, 8), 256, SM128>>>(
        xh, nullptr, wsrB, part, 4096, 256, nullptr, nullptr, nullptr, nullptr, nullptr);
    reduce_ln<<<256, 256>>>(part, sr_b, norm_g, norm_b, src);

    // fused k/v projections (M=2048, KTT=4)
    mma_gemm<EPI_ELU1, 3, 128, true, 4><<<dim3(16, 2, 2), 256, SM128>>>(
        src, nullptr, wkr, kmat, 256, 256, nullptr, nullptr, nullptr, wvr, vmat);

    kv_kernel<<<64, 256>>>(kmat, vmat, kvp, ksump);

    // q projection + fused linear attention -> msg (KTT=4)
    mma_gemm<EPI_ATTN, 0, 128, true, 4><<<dim3(256, 2), 256, SMATTN>>>(
        xh, nullptr, wqr, msg, 256, 256, kvp, ksump, nullptr, nullptr, nullptr);

    // merge projection + LN1 (NB=256, 512 thr, KTT=4)
    mma_gemm<EPI_LN, 0, 256, true, 4><<<dim3(256, 1), 512, SM256>>>(
        msg, nullptr, wmr, msgn, 256, 256, n1g, n1b, nullptr, nullptr, nullptr);

    // MLP1: concat(xh, msgn) @ w1^T -> relu (KTT=8)
    mma_gemm<EPI_RELU, 1, 128, true, 8><<<dim3(256, 4), 256, SM128>>>(
        xh, msgn, w1r, hmid, 512, 512, nullptr, nullptr, nullptr, nullptr, nullptr);

    // MLP2 + LN2 + residual -> out (NB=256, 512 thr, KTT=8, fp32 out)
    mma_gemm<EPI_LN_RESID, 0, 256, false, 8><<<dim3(256, 1), 512, SM256>>>(
        hmid, nullptr, w2r, out, 512, 256, n2g, n2b, x, nullptr, nullptr);
}